// round 1
// baseline (speedup 1.0000x reference)
#include <cuda_runtime.h>
#include <cuda_bf16.h>

// ChamferDistance: B=4, C=3, N=M=8192, fp32 inputs (B,C,N)/(B,C,M), scalar fp32 out.
//
// dist(n,m) = ||x_n||^2 - 2 x_n.y_m + ||y_m||^2 = 2*(h_x - (dot - h_y)),  h = 0.5*||.||^2
// min_m dist = 2*(h_x - max_m (dot - h_y))   -> 3 FFMA + 1 FMNMX per pair.

#define NPTS    8192
#define NBATCH  4
#define THREADS 128
#define CHUNK   2048        // target points staged in smem per iteration (32 KB)
#define NEG_INF (-3.402823466e38f)

__device__ float g_sum[2];  // [0] = sum of min_pred->targ, [1] = sum of min_targ->pred

__global__ void chamfer_zero_kernel() {
    g_sum[0] = 0.0f;
    g_sum[1] = 0.0f;
}

__global__ __launch_bounds__(THREADS)
void chamfer_main_kernel(const float* __restrict__ pred,
                         const float* __restrict__ targ) {
    const int dir = blockIdx.z;                 // 0: pred->targ, 1: targ->pred
    const float* __restrict__ X = dir ? targ : pred;   // query set
    const float* __restrict__ Y = dir ? pred : targ;   // database set
    const int b = blockIdx.y;
    const int n = blockIdx.x * THREADS + threadIdx.x;

    const float* __restrict__ Xb = X + (size_t)b * 3 * NPTS;
    const float* __restrict__ Yb = Y + (size_t)b * 3 * NPTS;

    // Query point in registers + its half-norm
    const float x0 = Xb[n];
    const float x1 = Xb[NPTS + n];
    const float x2 = Xb[2 * NPTS + n];
    const float hx = 0.5f * (x0 * x0 + x1 * x1 + x2 * x2);

    __shared__ float4 sh[CHUNK];          // {y0, y1, y2, 0.5*||y||^2}
    __shared__ float  wsum[THREADS / 32];

    // 4 independent max chains to break the FMNMX serial dependency
    float mx0 = NEG_INF, mx1 = NEG_INF, mx2 = NEG_INF, mx3 = NEG_INF;

    for (int base = 0; base < NPTS; base += CHUNK) {
        __syncthreads();
        #pragma unroll
        for (int i = threadIdx.x; i < CHUNK; i += THREADS) {
            float y0 = Yb[base + i];
            float y1 = Yb[NPTS + base + i];
            float y2 = Yb[2 * NPTS + base + i];
            float hy = 0.5f * (y0 * y0 + y1 * y1 + y2 * y2);
            sh[i] = make_float4(y0, y1, y2, hy);
        }
        __syncthreads();

        #pragma unroll 4
        for (int m = 0; m < CHUNK; m += 4) {
            float4 ya = sh[m + 0];
            float4 yb = sh[m + 1];
            float4 yc = sh[m + 2];
            float4 yd = sh[m + 3];

            float t0 = fmaf(x0, ya.x, -ya.w);
            float t1 = fmaf(x0, yb.x, -yb.w);
            float t2 = fmaf(x0, yc.x, -yc.w);
            float t3 = fmaf(x0, yd.x, -yd.w);
            t0 = fmaf(x1, ya.y, t0);
            t1 = fmaf(x1, yb.y, t1);
            t2 = fmaf(x1, yc.y, t2);
            t3 = fmaf(x1, yd.y, t3);
            t0 = fmaf(x2, ya.z, t0);
            t1 = fmaf(x2, yb.z, t1);
            t2 = fmaf(x2, yc.z, t2);
            t3 = fmaf(x2, yd.z, t3);
            mx0 = fmaxf(mx0, t0);
            mx1 = fmaxf(mx1, t1);
            mx2 = fmaxf(mx2, t2);
            mx3 = fmaxf(mx3, t3);
        }
    }

    const float smax = fmaxf(fmaxf(mx0, mx1), fmaxf(mx2, mx3));
    float d = 2.0f * (hx - smax);     // min squared distance for query point n

    // Block-wide sum of d, one atomic per block
    #pragma unroll
    for (int off = 16; off > 0; off >>= 1)
        d += __shfl_xor_sync(0xffffffffu, d, off);
    const int lane = threadIdx.x & 31;
    const int wid  = threadIdx.x >> 5;
    if (lane == 0) wsum[wid] = d;
    __syncthreads();
    if (threadIdx.x == 0) {
        float s = 0.0f;
        #pragma unroll
        for (int i = 0; i < THREADS / 32; i++) s += wsum[i];
        atomicAdd(&g_sum[dir], s);
    }
}

__global__ void chamfer_final_kernel(float* __restrict__ out) {
    const float inv = 1.0f / (float)(NBATCH * NPTS);
    out[0] = (g_sum[0] + g_sum[1]) * inv;
}

extern "C" void kernel_launch(void* const* d_in, const int* in_sizes, int n_in,
                              void* d_out, int out_size) {
    const float* pred = (const float*)d_in[0];
    const float* targ = (const float*)d_in[1];
    float* out = (float*)d_out;

    chamfer_zero_kernel<<<1, 1>>>();
    dim3 grid(NPTS / THREADS, NBATCH, 2);
    chamfer_main_kernel<<<grid, THREADS>>>(pred, targ);
    chamfer_final_kernel<<<1, 1>>>(out);
}

// round 2
// speedup vs baseline: 2.0382x; 2.0382x over previous
#include <cuda_runtime.h>
#include <cuda_bf16.h>

// ChamferDistance: B=4, C=3, N=M=8192, fp32.
// dist(n,m) = 2*hx - 2*(x.y - hy);  min_m dist = 2*hx - 2*max_m(x.y - hy)
// Packed fma.rn.f32x2 (Blackwell 2xFP32): 1.5 FFMA2 + 1 FMNMX per pair.
// Work split: (dir, batch, qtile 512, tchunk 512) = 2048 blocks, combined via float atomicMax.

#define NPTS     8192
#define NBATCH   4
#define THREADS  128
#define QPT      4            // queries per thread -> 512 queries per block
#define QTILE    (THREADS * QPT)
#define TCHUNK   512          // targets per block
#define NQT      (NPTS / QTILE)    // 16 query tiles
#define NTC      (NPTS / TCHUNK)   // 16 target chunks
#define NUNITS   (2 * NBATCH * NQT * NTC)   // 2048
#define NQUERY   (2 * NBATCH * NPTS)        // 65536

__device__ float g_mx[NQUERY];   // running max of (x.y - hy) per query
__device__ float g_hsum;         // sum of 2*hx over all queries (both dirs)

typedef unsigned long long u64;

__device__ __forceinline__ u64 fma2(u64 a, u64 b, u64 c) {
    u64 d;
    asm("fma.rn.f32x2 %0, %1, %2, %3;" : "=l"(d) : "l"(a), "l"(b), "l"(c));
    return d;
}
__device__ __forceinline__ u64 pack2(float x) {
    u64 d;
    asm("mov.b64 %0, {%1, %1};" : "=l"(d) : "f"(x));
    return d;
}
__device__ __forceinline__ void unpack2(u64 v, float& lo, float& hi) {
    asm("mov.b64 {%0, %1}, %2;" : "=f"(lo), "=f"(hi) : "l"(v));
}
__device__ __forceinline__ void lds_v2u64(unsigned addr, u64& a, u64& b) {
    asm volatile("ld.shared.v2.u64 {%0, %1}, [%2];" : "=l"(a), "=l"(b) : "r"(addr));
}
__device__ __forceinline__ void atomicMaxFloat(float* addr, float val) {
    if (val >= 0.0f) atomicMax((int*)addr, __float_as_int(val));
    else             atomicMin((unsigned*)addr, __float_as_uint(val));
}

__global__ void chamfer_init_kernel() {
    int i = blockIdx.x * blockDim.x + threadIdx.x;
    if (i < NQUERY) g_mx[i] = __int_as_float(0xff800000);  // -inf
    if (i == 0) g_hsum = 0.0f;
}

__global__ __launch_bounds__(THREADS)
void chamfer_main_kernel(const float* __restrict__ pred,
                         const float* __restrict__ targ) {
    const int u     = blockIdx.x;
    const int tc    = u & (NTC - 1);
    const int qt    = (u / NTC) & (NQT - 1);
    const int bd    = u / (NTC * NQT);
    const int b     = bd & (NBATCH - 1);
    const int dir   = bd >> 2;

    const float* __restrict__ X = dir ? targ : pred;
    const float* __restrict__ Y = dir ? pred : targ;
    const float* __restrict__ Xb = X + (size_t)b * 3 * NPTS;
    const float* __restrict__ Yb = Y + (size_t)b * 3 * NPTS;

    __shared__ float s_y0[TCHUNK], s_y1[TCHUNK], s_y2[TCHUNK], s_nh[TCHUNK];
    __shared__ float wsum[THREADS / 32];

    const int tid = threadIdx.x;

    // ---- stage target chunk into SoA smem: {y0, y1, y2, -0.5*||y||^2} ----
    const int tbase = tc * TCHUNK;
    #pragma unroll
    for (int i = tid; i < TCHUNK; i += THREADS) {
        float y0 = Yb[tbase + i];
        float y1 = Yb[NPTS + tbase + i];
        float y2 = Yb[2 * NPTS + tbase + i];
        s_y0[i] = y0;
        s_y1[i] = y1;
        s_y2[i] = y2;
        s_nh[i] = -0.5f * (y0 * y0 + y1 * y1 + y2 * y2);
    }

    // ---- query points (QPT per thread) in registers, packed broadcast ----
    const int qbase = qt * QTILE;
    u64 xp0[QPT], xp1[QPT], xp2[QPT];
    float hx[QPT];
    #pragma unroll
    for (int q = 0; q < QPT; q++) {
        int n = qbase + q * THREADS + tid;
        float x0 = Xb[n];
        float x1 = Xb[NPTS + n];
        float x2 = Xb[2 * NPTS + n];
        xp0[q] = pack2(x0);
        xp1[q] = pack2(x1);
        xp2[q] = pack2(x2);
        hx[q] = 0.5f * (x0 * x0 + x1 * x1 + x2 * x2);
    }
    __syncthreads();

    unsigned a0 = (unsigned)__cvta_generic_to_shared(s_y0);
    unsigned a1 = (unsigned)__cvta_generic_to_shared(s_y1);
    unsigned a2 = (unsigned)__cvta_generic_to_shared(s_y2);
    unsigned ah = (unsigned)__cvta_generic_to_shared(s_nh);

    float m0[QPT], m1[QPT];
    #pragma unroll
    for (int q = 0; q < QPT; q++) { m0[q] = -3.402823466e38f; m1[q] = m0[q]; }

    // ---- main loop: 4 targets per iteration, all uniform-address broadcast LDS ----
    #pragma unroll 2
    for (int j = 0; j < TCHUNK / 4; j++) {
        u64 A0, A1, B0, B1, C0, C1, H0, H1;
        unsigned off = j * 16;
        lds_v2u64(a0 + off, A0, A1);
        lds_v2u64(a1 + off, B0, B1);
        lds_v2u64(a2 + off, C0, C1);
        lds_v2u64(ah + off, H0, H1);

        #pragma unroll
        for (int q = 0; q < QPT; q++) {
            u64 t0 = fma2(xp0[q], A0, H0);
            u64 t1 = fma2(xp0[q], A1, H1);
            t0 = fma2(xp1[q], B0, t0);
            t1 = fma2(xp1[q], B1, t1);
            t0 = fma2(xp2[q], C0, t0);
            t1 = fma2(xp2[q], C1, t1);
            float l0, h0, l1, h1;
            unpack2(t0, l0, h0);
            unpack2(t1, l1, h1);
            m0[q] = fmaxf(m0[q], l0);
            m1[q] = fmaxf(m1[q], h0);
            m0[q] = fmaxf(m0[q], l1);
            m1[q] = fmaxf(m1[q], h1);
        }
    }

    // ---- fold partial max into global scratch ----
    const int gq0 = bd * NPTS + qbase + tid;
    #pragma unroll
    for (int q = 0; q < QPT; q++) {
        atomicMaxFloat(&g_mx[gq0 + q * THREADS], fmaxf(m0[q], m1[q]));
    }

    // ---- tchunk 0 contributes sum of 2*hx (each query counted once) ----
    if (tc == 0) {
        float s = 0.0f;
        #pragma unroll
        for (int q = 0; q < QPT; q++) s += 2.0f * hx[q];
        #pragma unroll
        for (int off = 16; off > 0; off >>= 1)
            s += __shfl_xor_sync(0xffffffffu, s, off);
        if ((tid & 31) == 0) wsum[tid >> 5] = s;
        __syncthreads();
        if (tid == 0) {
            float t = 0.0f;
            #pragma unroll
            for (int i = 0; i < THREADS / 32; i++) t += wsum[i];
            atomicAdd(&g_hsum, t);
        }
    }
}

__global__ __launch_bounds__(1024)
void chamfer_reduce_kernel(float* __restrict__ out) {
    __shared__ float wsum[32];
    float s = 0.0f;
    for (int i = threadIdx.x; i < NQUERY; i += 1024) s += g_mx[i];
    #pragma unroll
    for (int off = 16; off > 0; off >>= 1)
        s += __shfl_xor_sync(0xffffffffu, s, off);
    if ((threadIdx.x & 31) == 0) wsum[threadIdx.x >> 5] = s;
    __syncthreads();
    if (threadIdx.x == 0) {
        float t = 0.0f;
        #pragma unroll
        for (int i = 0; i < 32; i++) t += wsum[i];
        out[0] = (g_hsum - 2.0f * t) * (1.0f / (float)(NBATCH * NPTS));
    }
}

extern "C" void kernel_launch(void* const* d_in, const int* in_sizes, int n_in,
                              void* d_out, int out_size) {
    const float* pred = (const float*)d_in[0];
    const float* targ = (const float*)d_in[1];
    float* out = (float*)d_out;

    chamfer_init_kernel<<<NQUERY / 256, 256>>>();
    chamfer_main_kernel<<<NUNITS, THREADS>>>(pred, targ);
    chamfer_reduce_kernel<<<1, 1024>>>(out);
}